// round 12
// baseline (speedup 1.0000x reference)
#include <cuda_runtime.h>

// Problem dims (fixed by the dataset)
#define BB 8
#define CC 19
#define HH 512
#define WW 1024
#define HWW (HH*WW)
#define NPIX (BB*HWW)

#define TS 32   // UF tile 32x32

// flag-in-parent encoding
#define FLAGB 0x40000000
#define IDXM  0x3FFFFFFF

// seam slot counts (horizontal part vectorized 4 px/thread)
#define NSEAM_H4 (BB * 15 * WW / 4)     // 30720
#define NSEAM_V  (BB * 31 * HH)         // 126976
#define NSEAM_T  (NSEAM_H4 + NSEAM_V)

#define NLL_GRID (NPIX / 4 / 256)       // 4096 blocks

// ---------------- scratch (device globals; no allocation allowed) ----------
__device__ int            g_parent[NPIX];
__device__ unsigned char  g_wmask[NPIX];   // bit0=weak, bit1=strong
__device__ double         g_sum_nll;
__device__ double         g_sum_bnll;
__device__ unsigned long long g_cnt_valid;
__device__ unsigned long long g_cnt_b;
__device__ unsigned int   g_done = 0;

// ================= shared-memory union-find helpers ========================
__device__ __forceinline__ int find_s(int* sp, int x) {
    int p = sp[x];
    while (p != x) {
        int gp = sp[p];
        if (gp != p) sp[x] = gp;
        x = p; p = gp;
    }
    return x;
}

__device__ __forceinline__ void union_s(int* sp, int a, int b) {
    while (true) {
        a = find_s(sp, a);
        b = find_s(sp, b);
        if (a == b) return;
        if (a < b) { int t = a; a = b; b = t; }
        int old = atomicCAS(&sp[a], a, b);
        if (old == a) return;
        a = old;
    }
}

// ============ fused Sobel + NMS + threshold + tile-local UF + flags ========
// 32x32 tile, 256 threads, 4 px/thread
__global__ __launch_bounds__(256) void k_canny(const int* __restrict__ tgt) {
    __shared__ float simg[TS + 4][TS + 5];   // img halo 2, edge-clamped (+pad)
    __shared__ float smag[TS + 2][TS + 3];   // mag halo 1, 0 outside img (+pad)
    __shared__ unsigned char ssec[TS][TS];   // quantized sector for centers
    __shared__ int sp[TS * TS];
    __shared__ unsigned char lw[TS * TS];
    __shared__ unsigned char sfl[TS * TS];   // local root -> has strong member

    const int tid = threadIdx.x;
    const int b  = blockIdx.z;
    const int h0 = blockIdx.y * TS;
    const int w0 = blockIdx.x * TS;
    const int* timg = tgt + b * HWW;
    const int base = b * HWW;

    // zero the accumulators once (k_canny completes before any reader runs)
    if (blockIdx.x == 0 && blockIdx.y == 0 && blockIdx.z == 0 && tid == 0) {
        g_sum_nll = 0.0; g_sum_bnll = 0.0; g_cnt_valid = 0ULL; g_cnt_b = 0ULL;
    }

    // ---- image load: (target*255)&255, edge padded ----
    // interior 32x32: vectorized int4, no clamping needed
    {
        int l0 = tid * 4;
        int lr = l0 >> 5, lc = l0 & 31;
        int4 v = *(const int4*)(timg + (h0 + lr) * WW + w0 + lc);
        simg[2 + lr][2 + lc + 0] = (float)((v.x * 255) & 255);
        simg[2 + lr][2 + lc + 1] = (float)((v.y * 255) & 255);
        simg[2 + lr][2 + lc + 2] = (float)((v.z * 255) & 255);
        simg[2 + lr][2 + lc + 3] = (float)((v.w * 255) & 255);
    }
    // halo rows: rr in {0,1,34,35}, cc 0..35  (144 cells)
    if (tid < 144) {
        int rr = tid / 36, cc = tid - rr * 36;
        int rrs = (rr < 2) ? rr : rr + 32;
        int gh = min(max(h0 - 2 + rrs, 0), HH - 1);
        int gw = min(max(w0 - 2 + cc, 0), WW - 1);
        int t = __ldg(timg + gh * WW + gw);
        simg[rrs][cc] = (float)((t * 255) & 255);
    }
    // halo cols: rr 2..33, cc in {0,1,34,35}  (128 cells)
    if (tid < 128) {
        int r2 = tid >> 2, c2 = tid & 3;
        int rr = r2 + 2;
        int ccs = (c2 < 2) ? c2 : c2 + 32;
        int gh = h0 + r2;                 // in [h0, h0+31]: no clamp needed
        int gw = min(max(w0 - 2 + ccs, 0), WW - 1);
        int t = __ldg(timg + gh * WW + gw);
        simg[rr][ccs] = (float)((t * 255) & 255);
    }
    __syncthreads();

    // gradient once per halo-1 pixel: mag everywhere, sector for centers
    for (int l = tid; l < (TS + 2) * (TS + 2); l += 256) {
        int r = l / (TS + 2), c = l - r * (TS + 2);
        int gh = h0 - 1 + r, gw = w0 - 1 + c;
        float m = 0.f;
        float gx = 0.f, gy = 0.f;
        if (gh >= 0 && gh < HH && gw >= 0 && gw < WW) {
            float a00 = simg[r][c],     a01 = simg[r][c+1],     a02 = simg[r][c+2];
            float a10 = simg[r+1][c],                           a12 = simg[r+1][c+2];
            float a20 = simg[r+2][c],   a21 = simg[r+2][c+1],   a22 = simg[r+2][c+2];
            gx = (a02 + 2.f*a12 + a22) - (a00 + 2.f*a10 + a20);
            gy = (a20 + 2.f*a21 + a22) - (a00 + 2.f*a01 + a02);
            m = fabsf(gx) + fabsf(gy);
        }
        smag[r][c] = m;
        if (r >= 1 && r <= TS && c >= 1 && c <= TS) {
            float ax = fabsf(gx), ay = fabsf(gy);
            unsigned char sec;
            if (ay <= ax * 0.41421356f)      sec = 0;
            else if (ay >= ax * 2.41421356f) sec = 1;
            else sec = (gx * gy >= 0.f) ? 2 : 3;
            ssec[r - 1][c - 1] = sec;
        }
    }
    __syncthreads();

    // NMS + double threshold, 4 consecutive px per thread
    {
        int l0 = tid * 4;
        int lr = l0 >> 5, lcb = l0 & 31;
        uchar4 mout;
        unsigned char* mo = (unsigned char*)&mout;
#pragma unroll
        for (int k = 0; k < 4; k++) {
            int lc = lcb + k;
            int r = lr + 1, c = lc + 1;   // smag coords
            float mag = smag[r][c];
            unsigned char sec = ssec[lr][lc];
            float n1, n2;
            switch (sec) {
                case 0:  n1 = smag[r][c-1];   n2 = smag[r][c+1];   break;
                case 1:  n1 = smag[r-1][c];   n2 = smag[r+1][c];   break;
                case 2:  n1 = smag[r-1][c-1]; n2 = smag[r+1][c+1]; break;
                default: n1 = smag[r-1][c+1]; n2 = smag[r+1][c-1]; break;
            }
            bool keep = (mag >= n1) && (mag > n2);
            unsigned char m = 0;
            if (keep && mag > 50.f)  m |= 1;
            if (keep && mag > 150.f) m |= 2;
            mo[k] = m;
            lw[l0 + k] = m;
            sp[l0 + k] = l0 + k;
            sfl[l0 + k] = 0;
        }
        int gidx = base + (h0 + lr) * WW + w0 + lcb;
        *(uchar4*)(g_wmask + gidx) = mout;
    }
    __syncthreads();

    // local UF over weak pixels
#pragma unroll
    for (int k = 0; k < 4; k++) {
        int l = tid * 4 + k;
        if (!(lw[l] & 1)) continue;
        int lr = l >> 5, lc = l & 31;
        if (lc > 0 && (lw[l - 1] & 1)) union_s(sp, l, l - 1);
        if (lr > 0) {
            if (lw[l - 32] & 1)              union_s(sp, l, l - 32);
            if (lc > 0  && (lw[l - 33] & 1)) union_s(sp, l, l - 33);
            if (lc < 31 && (lw[l - 31] & 1)) union_s(sp, l, l - 31);
        }
    }
    __syncthreads();

    // mark local roots of components containing a strong pixel
#pragma unroll
    for (int k = 0; k < 4; k++) {
        int l = tid * 4 + k;
        if (lw[l] & 2) sfl[find_s(sp, l)] = 1;
    }
    __syncthreads();

    // write global parents; root entries carry the strong-flag in bit 30
#pragma unroll
    for (int k = 0; k < 4; k++) {
        int l = tid * 4 + k;
        if (!(lw[l] & 1)) continue;
        int root = find_s(sp, l);
        int lr = l >> 5, lc = l & 31;
        int groot = base + (h0 + (root >> 5)) * WW + (w0 + (root & 31));
        int gi    = base + (h0 + lr) * WW + (w0 + lc);
        int val = (l == root && sfl[root]) ? (groot | FLAGB) : groot;
        g_parent[gi] = val;
    }
}

// ============ global union-find with flag propagation ======================
__device__ __forceinline__ int uf_find(int* P, int x) {
    int p = P[x] & IDXM;
    while (p != x) {
        int gp = P[p] & IDXM;
        if (gp != p) P[x] = gp;   // halving: x is non-root, pointer-only entry
        x = p; p = gp;
    }
    return x;
}

// plant the strong flag on the (current) root of x's component
__device__ __forceinline__ void uf_setflag(int* P, int x) {
    while (true) {
        int r = uf_find(P, x);
        int old = atomicOr(&P[r], FLAGB);
        if ((old & IDXM) == r) return;   // landed on a root: done
        x = old & IDXM;                  // r was re-linked concurrently: chase
    }
}

__device__ __forceinline__ void uf_union(int* P, int a, int b) {
    while (true) {
        a = uf_find(P, a);
        b = uf_find(P, b);
        if (a == b) return;
        if (a < b) { int t = a; a = b; b = t; }
        int aval = P[a];
        if ((aval & IDXM) != a) continue;        // stale root, retry
        int old = atomicCAS(&P[a], aval, b);     // full-word compare: flag-safe
        if (old == aval) {
            if (aval & FLAGB) uf_setflag(P, b);  // carry flag to the new root
            return;
        }
        // lost the race: retry from current roots
    }
}

// ====== seam-direct cross-tile unions ======================================
// horizontal: 4 px/thread with uchar4 early-out; vertical: wi-fastest
__global__ __launch_bounds__(256) void k_seam() {
    int t = blockIdx.x * blockDim.x + threadIdx.x;
    if (t >= NSEAM_T) return;

    if (t < NSEAM_H4) {
        // horizontal seams: rows h = 32,64,...,480 (15/image), 4 px/thread
        int b  = t / (15 * (WW / 4));
        int r  = t - b * (15 * (WW / 4));
        int hi = r / (WW / 4);
        int w4 = (r - hi * (WW / 4)) * 4;
        int h  = (hi + 1) * TS;
        int base = b * HWW;
        int i0 = base + h * WW + w4;
        uchar4 cur = *(const uchar4*)(g_wmask + i0);
        unsigned int cw;
        memcpy(&cw, &cur, 4);
        if ((cw & 0x01010101u) == 0u) return;    // no weak px in this group
        unsigned char cm[4];
        memcpy(cm, &cur, 4);
        int rowup = base + (h - 1) * WW;
#pragma unroll
        for (int k = 0; k < 4; k++) {
            if (!(cm[k] & 1)) continue;
            int w = w4 + k;
            int i = i0 + k;
            if (g_wmask[rowup + w] & 1)                     uf_union(g_parent, i, rowup + w);
            if (w > 0      && (g_wmask[rowup + w - 1] & 1)) uf_union(g_parent, i, rowup + w - 1);
            if (w < WW - 1 && (g_wmask[rowup + w + 1] & 1)) uf_union(g_parent, i, rowup + w + 1);
        }
    } else {
        // vertical seams: cols w = 32,64,...,992 (31/image), wi FASTEST
        int t2 = t - NSEAM_H4;
        int wi = t2 % 31;
        int r  = t2 / 31;
        int h  = r % HH;
        int b  = r / HH;
        int w  = (wi + 1) * TS;
        int base = b * HWW;
        int i = base + h * WW + w;       // pixel with lc==0
        bool iw  = (g_wmask[i] & 1) != 0;
        bool lw_ = (g_wmask[i - 1] & 1) != 0;    // (h, w-1), lc==31
        if (iw && lw_) uf_union(g_parent, i, i - 1);
        // diagonals across the vertical seam (horizontal-seam rows covered above)
        if ((h & (TS - 1)) != 0) {
            int up = i - WW;
            if (iw  && (g_wmask[up - 1] & 1)) uf_union(g_parent, i, up - 1);
            if (lw_ && (g_wmask[up] & 1))     uf_union(g_parent, i - 1, up);
        }
    }
}

// ====== fused NLL + boundary reduce + final (last-block-done) ==============
__global__ __launch_bounds__(256, 4) void k_nllfused(const float* __restrict__ in,
                                                     const int* __restrict__ tgt,
                                                     float* __restrict__ out) {
    const int tid = threadIdx.x;
    int p0 = (blockIdx.x * 256 + tid) * 4;
    int b = p0 / HWW;
    int off = p0 - b * HWW;
    const float* basep = in + (size_t)b * (CC * HWW) + off;

    int4 t4 = *(const int4*)(tgt + p0);
    int tg[4] = {t4.x, t4.y, t4.z, t4.w};

    float s[4]  = {0.f, 0.f, 0.f, 0.f};
    float xt[4] = {0.f, 0.f, 0.f, 0.f};

#pragma unroll 1
    for (int c0 = 0; c0 < CC; c0 += 5) {
        const int CN = (CC - c0 < 5) ? (CC - c0) : 5;
        float f[5][4];
#pragma unroll
        for (int j = 0; j < 5; j++) {
            if (j < CN) {
                float4 v = __ldg((const float4*)(basep + (size_t)(c0 + j) * HWW));
                f[j][0] = v.x; f[j][1] = v.y; f[j][2] = v.z; f[j][3] = v.w;
            }
        }
#pragma unroll
        for (int j = 0; j < 5; j++) {
            if (j < CN) {
#pragma unroll
                for (int k = 0; k < 4; k++) {
                    s[k] += __expf(f[j][k]);
                    if (c0 + j == tg[k]) xt[k] = f[j][k];
                }
            }
        }
    }

    uchar4 m4 = *(const uchar4*)(g_wmask + p0);
    unsigned char mm[4] = {m4.x, m4.y, m4.z, m4.w};

    double v1 = 0.0, v2 = 0.0;
    unsigned int cv = 0, cb = 0;
#pragma unroll
    for (int k = 0; k < 4; k++) {
        bool valid = (tg[k] != 255);
        float nll = valid ? (__logf(s[k]) - xt[k]) : 0.f;
        v1 += (double)nll;
        cv += valid ? 1u : 0u;
        if (mm[k] & 1) {
            // read-only root chase; flag rides in the root's parent word
            int v = g_parent[p0 + k];
            int p = v & IDXM;
            int vp = g_parent[p];
            while ((vp & IDXM) != p) { p = vp & IDXM; vp = g_parent[p]; }
            if (vp & FLAGB) { v2 += (double)nll; cb++; }
        }
    }

    const unsigned int full = 0xFFFFFFFFu;
#pragma unroll
    for (int o = 16; o > 0; o >>= 1) {
        v1 += __shfl_down_sync(full, v1, o);
        v2 += __shfl_down_sync(full, v2, o);
        cv += __shfl_down_sync(full, cv, o);
        cb += __shfl_down_sync(full, cb, o);
    }
    __shared__ double sh1[8], sh2[8];
    __shared__ unsigned int shc[8], shb[8];
    int lane = tid & 31, wid = tid >> 5;
    if (lane == 0) { sh1[wid] = v1; sh2[wid] = v2; shc[wid] = cv; shb[wid] = cb; }
    __syncthreads();
    if (wid == 0) {
        v1 = (lane < 8) ? sh1[lane] : 0.0;
        v2 = (lane < 8) ? sh2[lane] : 0.0;
        cv = (lane < 8) ? shc[lane] : 0u;
        cb = (lane < 8) ? shb[lane] : 0u;
#pragma unroll
        for (int o = 4; o > 0; o >>= 1) {
            v1 += __shfl_down_sync(full, v1, o);
            v2 += __shfl_down_sync(full, v2, o);
            cv += __shfl_down_sync(full, cv, o);
            cb += __shfl_down_sync(full, cb, o);
        }
        if (lane == 0) {
            atomicAdd(&g_sum_nll, v1);
            atomicAdd(&g_cnt_valid, (unsigned long long)cv);
            if (cb > 0 || v2 != 0.0) {
                atomicAdd(&g_sum_bnll, v2);
                atomicAdd(&g_cnt_b, (unsigned long long)cb);
            }
            // last-block-done: finisher writes the loss (saves a launch)
            __threadfence();
            unsigned int n = atomicAdd(&g_done, 1);
            if (n == (unsigned int)(NLL_GRID - 1)) {
                g_done = 0;   // reset for next graph replay
                unsigned long long tv = g_cnt_valid;
                unsigned long long tb = g_cnt_b;
                double ce = g_sum_nll / (double)(tv > 0 ? tv : 1ULL);
                double loss = ce;
                if (tb > 0) loss += 10.0 * (g_sum_bnll / (double)tb);
                out[0] = (float)loss;
            }
        }
    }
}

// ---------------- launch ---------------------------------------------------

extern "C" void kernel_launch(void* const* d_in, const int* in_sizes, int n_in,
                              void* d_out, int out_size) {
    const float* input  = (const float*)d_in[0];
    const int*   target = (const int*)d_in[1];
    float* out = (float*)d_out;

    k_canny<<<dim3(WW / TS, HH / TS, BB), 256>>>(target);
    k_seam<<<(NSEAM_T + 255) / 256, 256>>>();
    k_nllfused<<<NLL_GRID, 256>>>(input, target, out);
}

// round 13
// speedup vs baseline: 1.0978x; 1.0978x over previous
#include <cuda_runtime.h>

// Problem dims (fixed by the dataset)
#define BB 8
#define CC 19
#define HH 512
#define WW 1024
#define HWW (HH*WW)
#define NPIX (BB*HWW)

#define TS 32   // UF tile 32x32

// flag-in-parent encoding
#define FLAGB 0x40000000
#define IDXM  0x3FFFFFFF

// seam slot counts
#define NSEAM_H (BB * 15 * WW)          // 15 interior seam rows per image
#define NSEAM_V (BB * 31 * HH)          // 31 interior seam cols per image
#define NSEAM   (NSEAM_H + NSEAM_V)

#define NLL_GRID (NPIX / 4 / 256)       // 4096 blocks

// ---------------- scratch (device globals; no allocation allowed) ----------
__device__ int            g_parent[NPIX];
__device__ unsigned char  g_wmask[NPIX];   // bit0=weak, bit1=strong
__device__ double         g_sum_nll;
__device__ double         g_sum_bnll;
__device__ unsigned long long g_cnt_valid;
__device__ unsigned long long g_cnt_b;
__device__ unsigned int   g_done = 0;

// ================= shared-memory union-find helpers ========================
__device__ __forceinline__ int find_s(int* sp, int x) {
    int p = sp[x];
    while (p != x) {
        int gp = sp[p];
        if (gp != p) sp[x] = gp;
        x = p; p = gp;
    }
    return x;
}

__device__ __forceinline__ void union_s(int* sp, int a, int b) {
    while (true) {
        a = find_s(sp, a);
        b = find_s(sp, b);
        if (a == b) return;
        if (a < b) { int t = a; a = b; b = t; }
        int old = atomicCAS(&sp[a], a, b);
        if (old == a) return;
        a = old;
    }
}

// ============ fused Sobel + NMS + threshold + tile-local UF + flags ========
// 32x32 tile, 256 threads, 4 px/thread (R9-measured load structure)
__global__ __launch_bounds__(256) void k_canny(const int* __restrict__ tgt) {
    __shared__ float simg[TS + 4][TS + 5];   // img halo 2, edge-clamped (+pad)
    __shared__ float smag[TS + 2][TS + 3];   // mag halo 1, 0 outside img (+pad)
    __shared__ unsigned char ssec[TS][TS];   // quantized sector for centers
    __shared__ int sp[TS * TS];
    __shared__ unsigned char lw[TS * TS];
    __shared__ unsigned char sfl[TS * TS];   // local root -> has strong member

    const int tid = threadIdx.x;
    const int b  = blockIdx.z;
    const int h0 = blockIdx.y * TS;
    const int w0 = blockIdx.x * TS;
    const int* timg = tgt + b * HWW;
    const int base = b * HWW;

    // zero the accumulators once (k_canny completes before any reader runs)
    if (blockIdx.x == 0 && blockIdx.y == 0 && blockIdx.z == 0 && tid == 0) {
        g_sum_nll = 0.0; g_sum_bnll = 0.0; g_cnt_valid = 0ULL; g_cnt_b = 0ULL;
    }

    // load image (target*255)%256, edge padded
    for (int l = tid; l < (TS + 4) * (TS + 4); l += 256) {
        int rr = l / (TS + 4), cc = l - rr * (TS + 4);
        int gh = min(max(h0 - 2 + rr, 0), HH - 1);
        int gw = min(max(w0 - 2 + cc, 0), WW - 1);
        int t = __ldg(timg + gh * WW + gw);
        simg[rr][cc] = (float)((t * 255) & 255);
    }
    __syncthreads();

    // gradient once per halo-1 pixel: mag everywhere, sector for centers
    for (int l = tid; l < (TS + 2) * (TS + 2); l += 256) {
        int r = l / (TS + 2), c = l - r * (TS + 2);
        int gh = h0 - 1 + r, gw = w0 - 1 + c;
        float m = 0.f;
        float gx = 0.f, gy = 0.f;
        if (gh >= 0 && gh < HH && gw >= 0 && gw < WW) {
            float a00 = simg[r][c],     a01 = simg[r][c+1],     a02 = simg[r][c+2];
            float a10 = simg[r+1][c],                           a12 = simg[r+1][c+2];
            float a20 = simg[r+2][c],   a21 = simg[r+2][c+1],   a22 = simg[r+2][c+2];
            gx = (a02 + 2.f*a12 + a22) - (a00 + 2.f*a10 + a20);
            gy = (a20 + 2.f*a21 + a22) - (a00 + 2.f*a01 + a02);
            m = fabsf(gx) + fabsf(gy);
        }
        smag[r][c] = m;
        if (r >= 1 && r <= TS && c >= 1 && c <= TS) {
            float ax = fabsf(gx), ay = fabsf(gy);
            unsigned char sec;
            if (ay <= ax * 0.41421356f)      sec = 0;
            else if (ay >= ax * 2.41421356f) sec = 1;
            else sec = (gx * gy >= 0.f) ? 2 : 3;
            ssec[r - 1][c - 1] = sec;
        }
    }
    __syncthreads();

    // NMS + double threshold, 4 consecutive px per thread
    {
        int l0 = tid * 4;
        int lr = l0 >> 5, lcb = l0 & 31;
        uchar4 mout;
        unsigned char* mo = (unsigned char*)&mout;
#pragma unroll
        for (int k = 0; k < 4; k++) {
            int lc = lcb + k;
            int r = lr + 1, c = lc + 1;   // smag coords
            float mag = smag[r][c];
            unsigned char sec = ssec[lr][lc];
            float n1, n2;
            switch (sec) {
                case 0:  n1 = smag[r][c-1];   n2 = smag[r][c+1];   break;
                case 1:  n1 = smag[r-1][c];   n2 = smag[r+1][c];   break;
                case 2:  n1 = smag[r-1][c-1]; n2 = smag[r+1][c+1]; break;
                default: n1 = smag[r-1][c+1]; n2 = smag[r+1][c-1]; break;
            }
            bool keep = (mag >= n1) && (mag > n2);
            unsigned char m = 0;
            if (keep && mag > 50.f)  m |= 1;
            if (keep && mag > 150.f) m |= 2;
            mo[k] = m;
            lw[l0 + k] = m;
            sp[l0 + k] = l0 + k;
            sfl[l0 + k] = 0;
        }
        int gidx = base + (h0 + lr) * WW + w0 + lcb;
        *(uchar4*)(g_wmask + gidx) = mout;
    }
    __syncthreads();

    // local UF over weak pixels
#pragma unroll
    for (int k = 0; k < 4; k++) {
        int l = tid * 4 + k;
        if (!(lw[l] & 1)) continue;
        int lr = l >> 5, lc = l & 31;
        if (lc > 0 && (lw[l - 1] & 1)) union_s(sp, l, l - 1);
        if (lr > 0) {
            if (lw[l - 32] & 1)              union_s(sp, l, l - 32);
            if (lc > 0  && (lw[l - 33] & 1)) union_s(sp, l, l - 33);
            if (lc < 31 && (lw[l - 31] & 1)) union_s(sp, l, l - 31);
        }
    }
    __syncthreads();

    // mark local roots of components containing a strong pixel
#pragma unroll
    for (int k = 0; k < 4; k++) {
        int l = tid * 4 + k;
        if (lw[l] & 2) sfl[find_s(sp, l)] = 1;
    }
    __syncthreads();

    // write global parents; root entries carry the strong-flag in bit 30
#pragma unroll
    for (int k = 0; k < 4; k++) {
        int l = tid * 4 + k;
        if (!(lw[l] & 1)) continue;
        int root = find_s(sp, l);
        int lr = l >> 5, lc = l & 31;
        int groot = base + (h0 + (root >> 5)) * WW + (w0 + (root & 31));
        int gi    = base + (h0 + lr) * WW + (w0 + lc);
        int val = (l == root && sfl[root]) ? (groot | FLAGB) : groot;
        g_parent[gi] = val;
    }
}

// ============ global union-find with flag propagation ======================
__device__ __forceinline__ int uf_find(int* P, int x) {
    int p = P[x] & IDXM;
    while (p != x) {
        int gp = P[p] & IDXM;
        if (gp != p) P[x] = gp;   // halving: x is non-root, pointer-only entry
        x = p; p = gp;
    }
    return x;
}

// plant the strong flag on the (current) root of x's component
__device__ __forceinline__ void uf_setflag(int* P, int x) {
    while (true) {
        int r = uf_find(P, x);
        int old = atomicOr(&P[r], FLAGB);
        if ((old & IDXM) == r) return;   // landed on a root: done
        x = old & IDXM;                  // r was re-linked concurrently: chase
    }
}

__device__ __forceinline__ void uf_union(int* P, int a, int b) {
    while (true) {
        a = uf_find(P, a);
        b = uf_find(P, b);
        if (a == b) return;
        if (a < b) { int t = a; a = b; b = t; }
        int aval = P[a];
        if ((aval & IDXM) != a) continue;        // stale root, retry
        int old = atomicCAS(&P[a], aval, b);     // full-word compare: flag-safe
        if (old == aval) {
            if (aval & FLAGB) uf_setflag(P, b);  // carry flag to the new root
            return;
        }
        // lost the race: retry from current roots
    }
}

// ====== seam-direct cross-tile unions: one thread per seam pixel slot ======
__global__ __launch_bounds__(256) void k_seam() {
    int t = blockIdx.x * blockDim.x + threadIdx.x;
    if (t >= NSEAM) return;

    if (t < NSEAM_H) {
        // horizontal seams: rows h = 32,64,...,480 (15 per image), w fastest
        int b  = t / (15 * WW);
        int r  = t - b * (15 * WW);
        int hi = r / WW;
        int w  = r - hi * WW;
        int h  = (hi + 1) * TS;
        int base = b * HWW;
        int i = base + h * WW + w;
        if (!(g_wmask[i] & 1)) return;
        int rowup = base + (h - 1) * WW;
        if (g_wmask[rowup + w] & 1)                     uf_union(g_parent, i, rowup + w);
        if (w > 0      && (g_wmask[rowup + w - 1] & 1)) uf_union(g_parent, i, rowup + w - 1);
        if (w < WW - 1 && (g_wmask[rowup + w + 1] & 1)) uf_union(g_parent, i, rowup + w + 1);
    } else {
        // vertical seams: cols w = 32,64,...,992 (31 per image), wi FASTEST
        int t2 = t - NSEAM_H;
        int wi = t2 % 31;
        int r  = t2 / 31;
        int h  = r % HH;
        int b  = r / HH;
        int w  = (wi + 1) * TS;
        int base = b * HWW;
        int i = base + h * WW + w;       // pixel with lc==0
        bool iw  = (g_wmask[i] & 1) != 0;
        bool lw_ = (g_wmask[i - 1] & 1) != 0;    // (h, w-1), lc==31
        if (iw && lw_) uf_union(g_parent, i, i - 1);
        // diagonals across the vertical seam (horizontal-seam rows covered above)
        if ((h & (TS - 1)) != 0) {
            int up = i - WW;
            if (iw  && (g_wmask[up - 1] & 1)) uf_union(g_parent, i, up - 1);
            if (lw_ && (g_wmask[up] & 1))     uf_union(g_parent, i - 1, up);
        }
    }
}

// ====== fused NLL + boundary reduce + final (chunked-5: best measured) =====
__global__ __launch_bounds__(256, 4) void k_nllfused(const float* __restrict__ in,
                                                     const int* __restrict__ tgt,
                                                     float* __restrict__ out) {
    const int tid = threadIdx.x;
    int p0 = (blockIdx.x * 256 + tid) * 4;
    int b = p0 / HWW;
    int off = p0 - b * HWW;
    const float* basep = in + (size_t)b * (CC * HWW) + off;

    int4 t4 = *(const int4*)(tgt + p0);
    int tg[4] = {t4.x, t4.y, t4.z, t4.w};

    float s[4]  = {0.f, 0.f, 0.f, 0.f};
    float xt[4] = {0.f, 0.f, 0.f, 0.f};

#pragma unroll 1
    for (int c0 = 0; c0 < CC; c0 += 5) {
        const int CN = (CC - c0 < 5) ? (CC - c0) : 5;
        float f[5][4];
#pragma unroll
        for (int j = 0; j < 5; j++) {
            if (j < CN) {
                float4 v = __ldg((const float4*)(basep + (size_t)(c0 + j) * HWW));
                f[j][0] = v.x; f[j][1] = v.y; f[j][2] = v.z; f[j][3] = v.w;
            }
        }
#pragma unroll
        for (int j = 0; j < 5; j++) {
            if (j < CN) {
#pragma unroll
                for (int k = 0; k < 4; k++) {
                    s[k] += __expf(f[j][k]);
                    if (c0 + j == tg[k]) xt[k] = f[j][k];
                }
            }
        }
    }

    uchar4 m4 = *(const uchar4*)(g_wmask + p0);
    unsigned char mm[4] = {m4.x, m4.y, m4.z, m4.w};

    double v1 = 0.0, v2 = 0.0;
    unsigned int cv = 0, cb = 0;
#pragma unroll
    for (int k = 0; k < 4; k++) {
        bool valid = (tg[k] != 255);
        float nll = valid ? (__logf(s[k]) - xt[k]) : 0.f;
        v1 += (double)nll;
        cv += valid ? 1u : 0u;
        if (mm[k] & 1) {
            // read-only root chase; flag rides in the root's parent word
            int v = g_parent[p0 + k];
            int p = v & IDXM;
            int vp = g_parent[p];
            while ((vp & IDXM) != p) { p = vp & IDXM; vp = g_parent[p]; }
            if (vp & FLAGB) { v2 += (double)nll; cb++; }
        }
    }

    const unsigned int full = 0xFFFFFFFFu;
#pragma unroll
    for (int o = 16; o > 0; o >>= 1) {
        v1 += __shfl_down_sync(full, v1, o);
        v2 += __shfl_down_sync(full, v2, o);
        cv += __shfl_down_sync(full, cv, o);
        cb += __shfl_down_sync(full, cb, o);
    }
    __shared__ double sh1[8], sh2[8];
    __shared__ unsigned int shc[8], shb[8];
    int lane = tid & 31, wid = tid >> 5;
    if (lane == 0) { sh1[wid] = v1; sh2[wid] = v2; shc[wid] = cv; shb[wid] = cb; }
    __syncthreads();
    if (wid == 0) {
        v1 = (lane < 8) ? sh1[lane] : 0.0;
        v2 = (lane < 8) ? sh2[lane] : 0.0;
        cv = (lane < 8) ? shc[lane] : 0u;
        cb = (lane < 8) ? shb[lane] : 0u;
#pragma unroll
        for (int o = 4; o > 0; o >>= 1) {
            v1 += __shfl_down_sync(full, v1, o);
            v2 += __shfl_down_sync(full, v2, o);
            cv += __shfl_down_sync(full, cv, o);
            cb += __shfl_down_sync(full, cb, o);
        }
        if (lane == 0) {
            atomicAdd(&g_sum_nll, v1);
            atomicAdd(&g_cnt_valid, (unsigned long long)cv);
            if (cb > 0 || v2 != 0.0) {
                atomicAdd(&g_sum_bnll, v2);
                atomicAdd(&g_cnt_b, (unsigned long long)cb);
            }
            // last-block-done: finisher writes the loss (saves a launch)
            __threadfence();
            unsigned int n = atomicAdd(&g_done, 1);
            if (n == (unsigned int)(NLL_GRID - 1)) {
                g_done = 0;   // reset for next graph replay
                unsigned long long tv = g_cnt_valid;
                unsigned long long tb = g_cnt_b;
                double ce = g_sum_nll / (double)(tv > 0 ? tv : 1ULL);
                double loss = ce;
                if (tb > 0) loss += 10.0 * (g_sum_bnll / (double)tb);
                out[0] = (float)loss;
            }
        }
    }
}

// ---------------- launch ---------------------------------------------------

extern "C" void kernel_launch(void* const* d_in, const int* in_sizes, int n_in,
                              void* d_out, int out_size) {
    const float* input  = (const float*)d_in[0];
    const int*   target = (const int*)d_in[1];
    float* out = (float*)d_out;

    k_canny<<<dim3(WW / TS, HH / TS, BB), 256>>>(target);
    k_seam<<<(NSEAM + 255) / 256, 256>>>();
    k_nllfused<<<NLL_GRID, 256>>>(input, target, out);
}

// round 14
// speedup vs baseline: 1.1408x; 1.0391x over previous
#include <cuda_runtime.h>

// Problem dims (fixed by the dataset)
#define BB 8
#define CC 19
#define HH 512
#define WW 1024
#define HWW (HH*WW)
#define NPIX (BB*HWW)

#define TS 32   // UF tile 32x32

// flag-in-parent encoding
#define FLAGB 0x40000000
#define IDXM  0x3FFFFFFF

// seam slot counts
#define NSEAM_H (BB * 15 * WW)          // 15 interior seam rows per image
#define NSEAM_V (BB * 31 * HH)          // 31 interior seam cols per image
#define NSEAM   (NSEAM_H + NSEAM_V)

#define NLL_GRID (NPIX / 4 / 256)       // 4096 blocks

// ---------------- scratch (device globals; no allocation allowed) ----------
__device__ int            g_parent[NPIX];
__device__ unsigned char  g_wmask[NPIX];   // bit0=weak, bit1=strong
__device__ double         g_sum_nll;
__device__ double         g_sum_bnll;
__device__ unsigned long long g_cnt_valid;
__device__ unsigned long long g_cnt_b;
__device__ unsigned int   g_done = 0;

// ================= shared-memory union-find helpers ========================
__device__ __forceinline__ int find_s(int* sp, int x) {
    int p = sp[x];
    while (p != x) {
        int gp = sp[p];
        if (gp != p) sp[x] = gp;
        x = p; p = gp;
    }
    return x;
}

__device__ __forceinline__ void union_s(int* sp, int a, int b) {
    while (true) {
        a = find_s(sp, a);
        b = find_s(sp, b);
        if (a == b) return;
        if (a < b) { int t = a; a = b; b = t; }
        int old = atomicCAS(&sp[a], a, b);
        if (old == a) return;
        a = old;
    }
}

// ============ fused Sobel + NMS + threshold + tile-local UF + flags ========
// 32x32 tile, 256 threads, 4 px/thread; separable register-resident gradients
__global__ __launch_bounds__(256) void k_canny(const int* __restrict__ tgt) {
    __shared__ float simg[TS + 4][TS + 5];   // img halo 2, edge-clamped (+pad)
    __shared__ float smag[TS + 2][TS + 3];   // mag halo 1, 0 outside img (+pad)
    __shared__ int sp[TS * TS];
    __shared__ unsigned char lw[TS * TS];
    __shared__ unsigned char sfl[TS * TS];   // local root -> has strong member

    const int tid = threadIdx.x;
    const int b  = blockIdx.z;
    const int h0 = blockIdx.y * TS;
    const int w0 = blockIdx.x * TS;
    const int* timg = tgt + b * HWW;
    const int base = b * HWW;

    // zero the accumulators once (k_canny completes before any reader runs)
    if (blockIdx.x == 0 && blockIdx.y == 0 && blockIdx.z == 0 && tid == 0) {
        g_sum_nll = 0.0; g_sum_bnll = 0.0; g_cnt_valid = 0ULL; g_cnt_b = 0ULL;
    }

    // load image (target*255)%256, edge padded
    for (int l = tid; l < (TS + 4) * (TS + 4); l += 256) {
        int rr = l / (TS + 4), cc = l - rr * (TS + 4);
        int gh = min(max(h0 - 2 + rr, 0), HH - 1);
        int gw = min(max(w0 - 2 + cc, 0), WW - 1);
        int t = __ldg(timg + gh * WW + gw);
        simg[rr][cc] = (float)((t * 255) & 255);
    }
    __syncthreads();

    const int lr  = tid >> 3;         // center row 0..31 (tile-relative)
    const int lcb = (tid & 7) * 4;    // center col base 0,4,...,28

    float magk[4];
    unsigned char seck[4];

    // ---- center mags: separable 3x6 window, 18 LDS, all exact integers ----
    {
        float r0[6], r1[6], r2[6];
#pragma unroll
        for (int j = 0; j < 6; j++) {
            r0[j] = simg[lr + 1][lcb + 1 + j];
            r1[j] = simg[lr + 2][lcb + 1 + j];
            r2[j] = simg[lr + 3][lcb + 1 + j];
        }
        float v[6], d[6];
#pragma unroll
        for (int j = 0; j < 6; j++) {
            v[j] = r0[j] + 2.f * r1[j] + r2[j];   // vertical sum  (for gx)
            d[j] = r2[j] - r0[j];                 // vertical diff (for gy)
        }
#pragma unroll
        for (int k = 0; k < 4; k++) {
            float gx = v[k + 2] - v[k];
            float gy = d[k] + 2.f * d[k + 1] + d[k + 2];
            float ax = fabsf(gx), ay = fabsf(gy);
            float m = ax + ay;
            unsigned char sec;
            if (ay <= ax * 0.41421356f)      sec = 0;
            else if (ay >= ax * 2.41421356f) sec = 1;
            else sec = (gx * gy >= 0.f) ? 2 : 3;
            magk[k] = m;
            seck[k] = sec;
            smag[lr + 1][lcb + 1 + k] = m;
        }
    }

    // ---- halo ring of smag: 132 cells, generic 8-LDS formula --------------
    if (tid < 132) {
        int mr, mc;
        if (tid < 68) {                      // rows 0 and 33, cols 0..33
            mr = (tid < 34) ? 0 : 33;
            mc = (tid < 34) ? tid : tid - 34;
        } else {                             // cols 0 and 33, rows 1..32
            int t2 = tid - 68;
            mc = (t2 < 32) ? 0 : 33;
            mr = 1 + (t2 & 31);
        }
        int gh = h0 + mr - 1, gw = w0 + mc - 1;
        float m = 0.f;
        if (gh >= 0 && gh < HH && gw >= 0 && gw < WW) {
            float a00 = simg[mr][mc],     a01 = simg[mr][mc+1],     a02 = simg[mr][mc+2];
            float a10 = simg[mr+1][mc],                             a12 = simg[mr+1][mc+2];
            float a20 = simg[mr+2][mc],   a21 = simg[mr+2][mc+1],   a22 = simg[mr+2][mc+2];
            float gx = (a02 + 2.f*a12 + a22) - (a00 + 2.f*a10 + a20);
            float gy = (a20 + 2.f*a21 + a22) - (a00 + 2.f*a01 + a02);
            m = fabsf(gx) + fabsf(gy);
        }
        smag[mr][mc] = m;
    }
    __syncthreads();

    // ---- NMS (branchless neighbor addressing) + thresholds ----------------
    {
        int l0 = tid * 4;
        uchar4 mout;
        unsigned char* mo = (unsigned char*)&mout;
        int mr = lr + 1;
#pragma unroll
        for (int k = 0; k < 4; k++) {
            int mc = lcb + 1 + k;
            int sec = seck[k];
            int dr = (sec == 0) ? 0 : -1;
            int dc = (sec == 1) ? 0 : ((sec == 3) ? 1 : -1);
            float n1 = smag[mr + dr][mc + dc];
            float n2 = smag[mr - dr][mc - dc];
            float mag = magk[k];
            bool keep = (mag >= n1) && (mag > n2);
            unsigned char m = 0;
            if (keep && mag > 50.f)  m |= 1;
            if (keep && mag > 150.f) m |= 2;
            mo[k] = m;
            lw[l0 + k] = m;
            sp[l0 + k] = l0 + k;
            sfl[l0 + k] = 0;
        }
        int gidx = base + (h0 + lr) * WW + w0 + lcb;
        *(uchar4*)(g_wmask + gidx) = mout;
    }
    __syncthreads();

    // local UF over weak pixels
#pragma unroll
    for (int k = 0; k < 4; k++) {
        int l = tid * 4 + k;
        if (!(lw[l] & 1)) continue;
        int rr = l >> 5, cc = l & 31;
        if (cc > 0 && (lw[l - 1] & 1)) union_s(sp, l, l - 1);
        if (rr > 0) {
            if (lw[l - 32] & 1)              union_s(sp, l, l - 32);
            if (cc > 0  && (lw[l - 33] & 1)) union_s(sp, l, l - 33);
            if (cc < 31 && (lw[l - 31] & 1)) union_s(sp, l, l - 31);
        }
    }
    __syncthreads();

    // mark local roots of components containing a strong pixel
#pragma unroll
    for (int k = 0; k < 4; k++) {
        int l = tid * 4 + k;
        if (lw[l] & 2) sfl[find_s(sp, l)] = 1;
    }
    __syncthreads();

    // write global parents; root entries carry the strong-flag in bit 30
#pragma unroll
    for (int k = 0; k < 4; k++) {
        int l = tid * 4 + k;
        if (!(lw[l] & 1)) continue;
        int root = find_s(sp, l);
        int rr = l >> 5, cc = l & 31;
        int groot = base + (h0 + (root >> 5)) * WW + (w0 + (root & 31));
        int gi    = base + (h0 + rr) * WW + (w0 + cc);
        int val = (l == root && sfl[root]) ? (groot | FLAGB) : groot;
        g_parent[gi] = val;
    }
}

// ============ global union-find with flag propagation ======================
__device__ __forceinline__ int uf_find(int* P, int x) {
    int p = P[x] & IDXM;
    while (p != x) {
        int gp = P[p] & IDXM;
        if (gp != p) P[x] = gp;   // halving: x is non-root, pointer-only entry
        x = p; p = gp;
    }
    return x;
}

// plant the strong flag on the (current) root of x's component
__device__ __forceinline__ void uf_setflag(int* P, int x) {
    while (true) {
        int r = uf_find(P, x);
        int old = atomicOr(&P[r], FLAGB);
        if ((old & IDXM) == r) return;   // landed on a root: done
        x = old & IDXM;                  // r was re-linked concurrently: chase
    }
}

__device__ __forceinline__ void uf_union(int* P, int a, int b) {
    while (true) {
        a = uf_find(P, a);
        b = uf_find(P, b);
        if (a == b) return;
        if (a < b) { int t = a; a = b; b = t; }
        int aval = P[a];
        if ((aval & IDXM) != a) continue;        // stale root, retry
        int old = atomicCAS(&P[a], aval, b);     // full-word compare: flag-safe
        if (old == aval) {
            if (aval & FLAGB) uf_setflag(P, b);  // carry flag to the new root
            return;
        }
        // lost the race: retry from current roots
    }
}

// ====== seam-direct cross-tile unions: one thread per seam pixel slot ======
__global__ __launch_bounds__(256) void k_seam() {
    int t = blockIdx.x * blockDim.x + threadIdx.x;
    if (t >= NSEAM) return;

    if (t < NSEAM_H) {
        // horizontal seams: rows h = 32,64,...,480 (15 per image), w fastest
        int b  = t / (15 * WW);
        int r  = t - b * (15 * WW);
        int hi = r / WW;
        int w  = r - hi * WW;
        int h  = (hi + 1) * TS;
        int base = b * HWW;
        int i = base + h * WW + w;
        if (!(g_wmask[i] & 1)) return;
        int rowup = base + (h - 1) * WW;
        if (g_wmask[rowup + w] & 1)                     uf_union(g_parent, i, rowup + w);
        if (w > 0      && (g_wmask[rowup + w - 1] & 1)) uf_union(g_parent, i, rowup + w - 1);
        if (w < WW - 1 && (g_wmask[rowup + w + 1] & 1)) uf_union(g_parent, i, rowup + w + 1);
    } else {
        // vertical seams: cols w = 32,64,...,992 (31 per image), wi FASTEST
        int t2 = t - NSEAM_H;
        int wi = t2 % 31;
        int r  = t2 / 31;
        int h  = r % HH;
        int b  = r / HH;
        int w  = (wi + 1) * TS;
        int base = b * HWW;
        int i = base + h * WW + w;       // pixel with lc==0
        bool iw  = (g_wmask[i] & 1) != 0;
        bool lw_ = (g_wmask[i - 1] & 1) != 0;    // (h, w-1), lc==31
        if (iw && lw_) uf_union(g_parent, i, i - 1);
        // diagonals across the vertical seam (horizontal-seam rows covered above)
        if ((h & (TS - 1)) != 0) {
            int up = i - WW;
            if (iw  && (g_wmask[up - 1] & 1)) uf_union(g_parent, i, up - 1);
            if (lw_ && (g_wmask[up] & 1))     uf_union(g_parent, i - 1, up);
        }
    }
}

// ====== fused NLL + boundary reduce + final (chunked-5: best measured) =====
__global__ __launch_bounds__(256, 4) void k_nllfused(const float* __restrict__ in,
                                                     const int* __restrict__ tgt,
                                                     float* __restrict__ out) {
    const int tid = threadIdx.x;
    int p0 = (blockIdx.x * 256 + tid) * 4;
    int b = p0 / HWW;
    int off = p0 - b * HWW;
    const float* basep = in + (size_t)b * (CC * HWW) + off;

    int4 t4 = *(const int4*)(tgt + p0);
    int tg[4] = {t4.x, t4.y, t4.z, t4.w};

    float s[4]  = {0.f, 0.f, 0.f, 0.f};
    float xt[4] = {0.f, 0.f, 0.f, 0.f};

#pragma unroll 1
    for (int c0 = 0; c0 < CC; c0 += 5) {
        const int CN = (CC - c0 < 5) ? (CC - c0) : 5;
        float f[5][4];
#pragma unroll
        for (int j = 0; j < 5; j++) {
            if (j < CN) {
                float4 v = __ldg((const float4*)(basep + (size_t)(c0 + j) * HWW));
                f[j][0] = v.x; f[j][1] = v.y; f[j][2] = v.z; f[j][3] = v.w;
            }
        }
#pragma unroll
        for (int j = 0; j < 5; j++) {
            if (j < CN) {
#pragma unroll
                for (int k = 0; k < 4; k++) {
                    s[k] += __expf(f[j][k]);
                    if (c0 + j == tg[k]) xt[k] = f[j][k];
                }
            }
        }
    }

    uchar4 m4 = *(const uchar4*)(g_wmask + p0);
    unsigned char mm[4] = {m4.x, m4.y, m4.z, m4.w};

    double v1 = 0.0, v2 = 0.0;
    unsigned int cv = 0, cb = 0;
#pragma unroll
    for (int k = 0; k < 4; k++) {
        bool valid = (tg[k] != 255);
        float nll = valid ? (__logf(s[k]) - xt[k]) : 0.f;
        v1 += (double)nll;
        cv += valid ? 1u : 0u;
        if (mm[k] & 1) {
            // read-only root chase; flag rides in the root's parent word
            int v = g_parent[p0 + k];
            int p = v & IDXM;
            int vp = g_parent[p];
            while ((vp & IDXM) != p) { p = vp & IDXM; vp = g_parent[p]; }
            if (vp & FLAGB) { v2 += (double)nll; cb++; }
        }
    }

    const unsigned int full = 0xFFFFFFFFu;
#pragma unroll
    for (int o = 16; o > 0; o >>= 1) {
        v1 += __shfl_down_sync(full, v1, o);
        v2 += __shfl_down_sync(full, v2, o);
        cv += __shfl_down_sync(full, cv, o);
        cb += __shfl_down_sync(full, cb, o);
    }
    __shared__ double sh1[8], sh2[8];
    __shared__ unsigned int shc[8], shb[8];
    int lane = tid & 31, wid = tid >> 5;
    if (lane == 0) { sh1[wid] = v1; sh2[wid] = v2; shc[wid] = cv; shb[wid] = cb; }
    __syncthreads();
    if (wid == 0) {
        v1 = (lane < 8) ? sh1[lane] : 0.0;
        v2 = (lane < 8) ? sh2[lane] : 0.0;
        cv = (lane < 8) ? shc[lane] : 0u;
        cb = (lane < 8) ? shb[lane] : 0u;
#pragma unroll
        for (int o = 4; o > 0; o >>= 1) {
            v1 += __shfl_down_sync(full, v1, o);
            v2 += __shfl_down_sync(full, v2, o);
            cv += __shfl_down_sync(full, cv, o);
            cb += __shfl_down_sync(full, cb, o);
        }
        if (lane == 0) {
            atomicAdd(&g_sum_nll, v1);
            atomicAdd(&g_cnt_valid, (unsigned long long)cv);
            if (cb > 0 || v2 != 0.0) {
                atomicAdd(&g_sum_bnll, v2);
                atomicAdd(&g_cnt_b, (unsigned long long)cb);
            }
            // last-block-done: finisher writes the loss (saves a launch)
            __threadfence();
            unsigned int n = atomicAdd(&g_done, 1);
            if (n == (unsigned int)(NLL_GRID - 1)) {
                g_done = 0;   // reset for next graph replay
                unsigned long long tv = g_cnt_valid;
                unsigned long long tb = g_cnt_b;
                double ce = g_sum_nll / (double)(tv > 0 ? tv : 1ULL);
                double loss = ce;
                if (tb > 0) loss += 10.0 * (g_sum_bnll / (double)tb);
                out[0] = (float)loss;
            }
        }
    }
}

// ---------------- launch ---------------------------------------------------

extern "C" void kernel_launch(void* const* d_in, const int* in_sizes, int n_in,
                              void* d_out, int out_size) {
    const float* input  = (const float*)d_in[0];
    const int*   target = (const int*)d_in[1];
    float* out = (float*)d_out;

    k_canny<<<dim3(WW / TS, HH / TS, BB), 256>>>(target);
    k_seam<<<(NSEAM + 255) / 256, 256>>>();
    k_nllfused<<<NLL_GRID, 256>>>(input, target, out);
}